// round 2
// baseline (speedup 1.0000x reference)
#include <cuda_runtime.h>

// Problem constants
#define NN   16384
#define BB   512
#define NNZE 131072
#define NB   (NN * (size_t)BB)

// Scratch (device globals — no runtime allocation allowed)
__device__ float g_h0[NB];          // h ping buffer, (N, B) layout
__device__ float g_h1[NB];          // h pong buffer
__device__ float g_c[NB];           // cell state, (N, B) layout
__device__ int   g_cnt[NN];         // per-column counts
__device__ int   g_ptr[NN + 1];     // CSC column pointers
__device__ int   g_fill[NN];        // scatter cursors
__device__ int   g_rows[NNZE];      // CSC row indices
__device__ float g_vals[NNZE];      // CSC values
__device__ int   g_is64;            // 1 if sparse_indices is int64, 0 if int32

// ---------------------------------------------------------------------------
// Math helpers (accurate route: ~1e-6 rel err, 2 MUFU each)
// ---------------------------------------------------------------------------
__device__ __forceinline__ float sigf(float x) {
    float e = __expf(-x);
    return __fdividef(1.0f, 1.0f + e);
}
__device__ __forceinline__ float tanhacc(float x) {
    // tanh(x) = 2*sigmoid(2x) - 1
    return fmaf(2.0f, sigf(2.0f * x), -1.0f);
}

// ---------------------------------------------------------------------------
// Index dtype detection: if int64, every odd 32-bit word (high word of a
// non-negative value < 2^31) is zero. If int32, odd words are random values
// in [0, 16384) and are ~never all zero across 1024 samples.
// ---------------------------------------------------------------------------
__global__ void k_detect(const int* __restrict__ p) {
    if (threadIdx.x == 0) {
        int nz = 0;
        for (int k = 1; k < 2048; k += 2) nz += (p[k] != 0);
        g_is64 = (nz == 0) ? 1 : 0;
    }
}

__device__ __forceinline__ void get_rc(const void* si, int e, int& r, int& c) {
    if (g_is64) {
        const long long* q = (const long long*)si;
        r = (int)q[2 * e];
        c = (int)q[2 * e + 1];
    } else {
        const int* q = (const int*)si;
        r = q[2 * e];
        c = q[2 * e + 1];
    }
}

// ---------------------------------------------------------------------------
// CSC construction
// ---------------------------------------------------------------------------
__global__ void k_zero_cnt() {
    g_cnt[blockIdx.x * 256 + threadIdx.x] = 0;
}

__global__ void k_count(const void* __restrict__ si) {
    int e = blockIdx.x * 256 + threadIdx.x;
    int r, c;
    get_rc(si, e, r, c);
    atomicAdd(&g_cnt[c], 1);
}

// Exclusive scan of 16384 counts, single block of 1024 threads (16 per thread).
__global__ void k_scan() {
    __shared__ int wsum[32];
    int t = threadIdx.x;
    int lane = t & 31, wid = t >> 5;
    int base = t * 16;
    int loc[16];
    int s = 0;
#pragma unroll
    for (int i = 0; i < 16; i++) { loc[i] = s; s += g_cnt[base + i]; }
    int v = s;
#pragma unroll
    for (int o = 1; o < 32; o <<= 1) {
        int u = __shfl_up_sync(0xffffffff, v, o);
        if (lane >= o) v += u;
    }
    if (lane == 31) wsum[wid] = v;
    __syncthreads();
    if (wid == 0) {
        int w = wsum[lane];
#pragma unroll
        for (int o = 1; o < 32; o <<= 1) {
            int u = __shfl_up_sync(0xffffffff, w, o);
            if (lane >= o) w += u;
        }
        wsum[lane] = w;
    }
    __syncthreads();
    int prefix = (v - s) + (wid ? wsum[wid - 1] : 0);
#pragma unroll
    for (int i = 0; i < 16; i++) {
        int p = prefix + loc[i];
        g_ptr[base + i]  = p;
        g_fill[base + i] = p;
    }
    if (t == 1023) g_ptr[NN] = prefix + s;
}

__global__ void k_scatter(const void* __restrict__ si, const float* __restrict__ kv) {
    int e = blockIdx.x * 256 + threadIdx.x;
    int r, c;
    get_rc(si, e, r, c);
    int p = atomicAdd(&g_fill[c], 1);
    g_rows[p] = r;
    g_vals[p] = kv[e];
}

// ---------------------------------------------------------------------------
// Transpose in: x (B,N) row-major -> g_h0 (N,B); also zero cell state.
// 32x32 tiles, block (32,8).
// ---------------------------------------------------------------------------
__global__ void k_init(const float* __restrict__ x) {
    __shared__ float tile[32][33];
    int nb = blockIdx.x, bb = blockIdx.y;
    int tx = threadIdx.x, ty = threadIdx.y;
#pragma unroll
    for (int i = 0; i < 4; i++) {
        int b = bb * 32 + ty + i * 8;
        int n = nb * 32 + tx;
        tile[ty + i * 8][tx] = x[(size_t)b * NN + n];   // tile[b_local][n_local]
    }
    __syncthreads();
#pragma unroll
    for (int i = 0; i < 4; i++) {
        int n = nb * 32 + ty + i * 8;
        int b = bb * 32 + tx;
        size_t idx = (size_t)n * BB + b;
        g_h0[idx] = tile[tx][ty + i * 8];               // tile[b_local=tx][n_local]
        g_c[idx]  = 0.0f;
    }
}

// Transpose out: g_h0 (N,B) -> out (B,N) row-major.
__global__ void k_out(float* __restrict__ out) {
    __shared__ float tile[32][33];
    int nb = blockIdx.x, bb = blockIdx.y;
    int tx = threadIdx.x, ty = threadIdx.y;
#pragma unroll
    for (int i = 0; i < 4; i++) {
        int n = nb * 32 + ty + i * 8;
        int b = bb * 32 + tx;
        tile[ty + i * 8][tx] = g_h0[(size_t)n * BB + b]; // tile[n_local][b_local]
    }
    __syncthreads();
#pragma unroll
    for (int i = 0; i < 4; i++) {
        int b = bb * 32 + ty + i * 8;
        int n = nb * 32 + tx;
        out[(size_t)b * NN + n] = tile[tx][ty + i * 8];  // tile[n_local=tx][b_local]
    }
}

// ---------------------------------------------------------------------------
// One reservoir iteration, fused SpMM (gather, CSC) + LSTM gates.
// One block per output column c; 128 threads x float4 covers B=512.
// ---------------------------------------------------------------------------
__global__ void __launch_bounds__(128) k_iter(
    int src,
    const float* __restrict__ bi, const float* __restrict__ bf,
    const float* __restrict__ bo, const float* __restrict__ bg)
{
    int c = blockIdx.x;
    int t = threadIdx.x;
    const float* __restrict__ hin  = src ? g_h1 : g_h0;
    float* __restrict__       hout = src ? g_h0 : g_h1;

    int e0 = __ldg(&g_ptr[c]);
    int e1 = __ldg(&g_ptr[c + 1]);

    float4 acc = make_float4(0.f, 0.f, 0.f, 0.f);
    for (int e = e0; e < e1; ++e) {
        int   r = __ldg(&g_rows[e]);
        float v = __ldg(&g_vals[e]);
        float4 hv = *reinterpret_cast<const float4*>(hin + (size_t)r * BB + (t << 2));
        acc.x = fmaf(v, hv.x, acc.x);
        acc.y = fmaf(v, hv.y, acc.y);
        acc.z = fmaf(v, hv.z, acc.z);
        acc.w = fmaf(v, hv.w, acc.w);
    }

    float vbi = __ldg(&bi[c]), vbf = __ldg(&bf[c]);
    float vbo = __ldg(&bo[c]), vbg = __ldg(&bg[c]);

    size_t o = (size_t)c * BB + (t << 2);
    float4 cold = *reinterpret_cast<const float4*>(g_c + o);

    float z[4]  = {acc.x, acc.y, acc.z, acc.w};
    float co[4] = {cold.x, cold.y, cold.z, cold.w};
    float cn[4], hn[4];
#pragma unroll
    for (int k = 0; k < 4; k++) {
        float ii = sigf(z[k] + vbi);
        float ff = sigf(z[k] + vbf);
        float oo = sigf(z[k] + vbo);
        float gg = tanhacc(z[k] + vbg);
        cn[k] = fmaf(ff, co[k], ii * gg);
        hn[k] = oo * tanhacc(cn[k]);
    }

    *reinterpret_cast<float4*>(g_c + o)  = make_float4(cn[0], cn[1], cn[2], cn[3]);
    *reinterpret_cast<float4*>(hout + o) = make_float4(hn[0], hn[1], hn[2], hn[3]);
}

// ---------------------------------------------------------------------------
// Launch
// ---------------------------------------------------------------------------
extern "C" void kernel_launch(void* const* d_in, const int* in_sizes, int n_in,
                              void* d_out, int out_size)
{
    const float* x  = (const float*)d_in[0];
    const float* kv = (const float*)d_in[1];
    const float* bi = (const float*)d_in[2];
    const float* bf = (const float*)d_in[3];
    const float* bo = (const float*)d_in[4];
    const float* bg = (const float*)d_in[5];
    const void*  si = d_in[6];

    // Sparse preprocessing: dtype detect, count, scan, scatter
    k_detect<<<1, 32>>>((const int*)si);
    k_zero_cnt<<<NN / 256, 256>>>();
    k_count<<<NNZE / 256, 256>>>(si);
    k_scan<<<1, 1024>>>();
    k_scatter<<<NNZE / 256, 256>>>(si, kv);

    // Transpose input to (N,B), zero cell state
    dim3 tb(32, 8);
    dim3 tg(NN / 32, BB / 32);
    k_init<<<tg, tb>>>(x);

    // 4 reservoir iterations (ping-pong: 0->1->0->1->0, result lands in g_h0)
    int src = 0;
    for (int it = 0; it < 4; ++it) {
        k_iter<<<NN, 128>>>(src, bi, bf, bo, bg);
        src ^= 1;
    }

    // Transpose result back to (B,N)
    k_out<<<tg, tb>>>((float*)d_out);
}

// round 4
// speedup vs baseline: 1.8493x; 1.8493x over previous
#include <cuda_runtime.h>

// Problem constants
#define NN    16384
#define BB    512
#define NNZE  131072
#define CAP   64                     // padded CSC capacity per column
#define NB    (NN * (size_t)BB)

// Scratch (device globals — no runtime allocation allowed)
__device__ float  g_h0[NB];          // h ping buffer, (N, B) layout
__device__ float  g_h1[NB];          // h pong buffer
__device__ float  g_c[NB];           // cell state, (N, B) layout
__device__ int    g_cnt[NN];         // per-column counts (atomic fill cursors)
__device__ float2 g_ent[NN * CAP];   // padded CSC entries: {row_as_float_bits, val}
__device__ int    g_is64;            // 1 if sparse_indices is int64, 0 if int32

// ---------------------------------------------------------------------------
// Fast gate math: MUFU.TANH (1 op), sigmoid via tanh identity.
// ---------------------------------------------------------------------------
__device__ __forceinline__ float tanh_ap(float x) {
    float y;
    asm("tanh.approx.f32 %0, %1;" : "=f"(y) : "f"(x));
    return y;
}
__device__ __forceinline__ float sig_ap(float x) {
    // sigmoid(x) = 0.5 * tanh(0.5 x) + 0.5
    return fmaf(0.5f, tanh_ap(0.5f * x), 0.5f);
}

// ---------------------------------------------------------------------------
// Index dtype detection: if int64, the high 32-bit word of every (non-negative,
// < 2^31) value is zero. Sample 512 odd words with a warp + ballot.
// ---------------------------------------------------------------------------
__global__ void k_detect(const int* __restrict__ p) {
    int t = threadIdx.x;
    int nz = 0;
#pragma unroll
    for (int i = 0; i < 16; i++) nz |= p[2 * (t + 32 * i) + 1];
    unsigned m = __ballot_sync(0xffffffffu, nz != 0);
    if (t == 0) g_is64 = (m == 0) ? 1 : 0;
}

__device__ __forceinline__ void get_rc(const void* si, int e, int& r, int& c) {
    if (g_is64) {
        const long long* q = (const long long*)si;
        r = (int)q[2 * e];
        c = (int)q[2 * e + 1];
    } else {
        const int* q = (const int*)si;
        r = q[2 * e];
        c = q[2 * e + 1];
    }
}

// ---------------------------------------------------------------------------
// Padded CSC build: zero counts, then single atomic-fill pass.
// ---------------------------------------------------------------------------
__global__ void k_zero_cnt() {
    g_cnt[blockIdx.x * 1024 + threadIdx.x] = 0;
}

__global__ void k_build(const void* __restrict__ si, const float* __restrict__ kv) {
    int e = blockIdx.x * 256 + threadIdx.x;
    int r, c;
    get_rc(si, e, r, c);
    int p = atomicAdd(&g_cnt[c], 1);
    if (p < CAP) {
        g_ent[(c << 6) + p] = make_float2(__int_as_float(r), kv[e]);
    }
}

// ---------------------------------------------------------------------------
// Transpose in: x (B,N) row-major -> g_h0 (N,B); also zero cell state.
// 32x32 tiles, block (32,8).
// ---------------------------------------------------------------------------
__global__ void k_init(const float* __restrict__ x) {
    __shared__ float tile[32][33];
    int nb = blockIdx.x, bb = blockIdx.y;
    int tx = threadIdx.x, ty = threadIdx.y;
#pragma unroll
    for (int i = 0; i < 4; i++) {
        int b = bb * 32 + ty + i * 8;
        int n = nb * 32 + tx;
        tile[ty + i * 8][tx] = x[(size_t)b * NN + n];
    }
    __syncthreads();
#pragma unroll
    for (int i = 0; i < 4; i++) {
        int n = nb * 32 + ty + i * 8;
        int b = bb * 32 + tx;
        size_t idx = (size_t)n * BB + b;
        g_h0[idx] = tile[tx][ty + i * 8];
        g_c[idx]  = 0.0f;
    }
}

// Transpose out: g_h0 (N,B) -> out (B,N) row-major.
__global__ void k_out(float* __restrict__ out) {
    __shared__ float tile[32][33];
    int nb = blockIdx.x, bb = blockIdx.y;
    int tx = threadIdx.x, ty = threadIdx.y;
#pragma unroll
    for (int i = 0; i < 4; i++) {
        int n = nb * 32 + ty + i * 8;
        int b = bb * 32 + tx;
        tile[ty + i * 8][tx] = g_h0[(size_t)n * BB + b];
    }
    __syncthreads();
#pragma unroll
    for (int i = 0; i < 4; i++) {
        int b = bb * 32 + ty + i * 8;
        int n = nb * 32 + tx;
        out[(size_t)b * NN + n] = tile[tx][ty + i * 8];
    }
}

// ---------------------------------------------------------------------------
// One reservoir iteration: fused gather-SpMM (padded CSC) + LSTM gates.
// One block per output column c; 128 threads x float4 covers B=512.
// ---------------------------------------------------------------------------
__global__ void __launch_bounds__(128) k_iter(
    int src,
    const float* __restrict__ bi, const float* __restrict__ bf,
    const float* __restrict__ bo, const float* __restrict__ bg)
{
    int c = blockIdx.x;
    int t = threadIdx.x;
    const float* __restrict__ hin  = src ? g_h1 : g_h0;
    float* __restrict__       hout = src ? g_h0 : g_h1;

    int cnt = __ldg(&g_cnt[c]);
    const float2* __restrict__ ep = g_ent + (c << 6);

    float4 acc = make_float4(0.f, 0.f, 0.f, 0.f);
    int boff = t << 2;
    for (int e = 0; e < cnt; ++e) {
        float2 en = __ldg(&ep[e]);
        int   r = __float_as_int(en.x);
        float v = en.y;
        float4 hv = *reinterpret_cast<const float4*>(hin + (size_t)r * BB + boff);
        acc.x = fmaf(v, hv.x, acc.x);
        acc.y = fmaf(v, hv.y, acc.y);
        acc.z = fmaf(v, hv.z, acc.z);
        acc.w = fmaf(v, hv.w, acc.w);
    }

    float vbi = __ldg(&bi[c]), vbf = __ldg(&bf[c]);
    float vbo = __ldg(&bo[c]), vbg = __ldg(&bg[c]);

    size_t o = (size_t)c * BB + boff;
    float4 cold = *reinterpret_cast<const float4*>(g_c + o);

    float z[4]  = {acc.x, acc.y, acc.z, acc.w};
    float co[4] = {cold.x, cold.y, cold.z, cold.w};
    float cn[4], hn[4];
#pragma unroll
    for (int k = 0; k < 4; k++) {
        float ii = sig_ap(z[k] + vbi);
        float ff = sig_ap(z[k] + vbf);
        float oo = sig_ap(z[k] + vbo);
        float gg = tanh_ap(z[k] + vbg);
        cn[k] = fmaf(ff, co[k], ii * gg);
        hn[k] = oo * tanh_ap(cn[k]);
    }

    *reinterpret_cast<float4*>(g_c + o)  = make_float4(cn[0], cn[1], cn[2], cn[3]);
    *reinterpret_cast<float4*>(hout + o) = make_float4(hn[0], hn[1], hn[2], hn[3]);
}

// ---------------------------------------------------------------------------
// Launch
// ---------------------------------------------------------------------------
extern "C" void kernel_launch(void* const* d_in, const int* in_sizes, int n_in,
                              void* d_out, int out_size)
{
    const float* x  = (const float*)d_in[0];
    const float* kv = (const float*)d_in[1];
    const float* bi = (const float*)d_in[2];
    const float* bf = (const float*)d_in[3];
    const float* bo = (const float*)d_in[4];
    const float* bg = (const float*)d_in[5];
    const void*  si = d_in[6];

    // Sparse preprocessing: dtype detect, zero counts, one atomic-fill pass
    k_detect<<<1, 32>>>((const int*)si);
    k_zero_cnt<<<NN / 1024, 1024>>>();
    k_build<<<NNZE / 256, 256>>>(si, kv);

    // Transpose input to (N,B), zero cell state
    dim3 tb(32, 8);
    dim3 tg(NN / 32, BB / 32);
    k_init<<<tg, tb>>>(x);

    // 4 reservoir iterations (ping-pong: 0->1->0->1->0, result lands in g_h0)
    int src = 0;
    for (int it = 0; it < 4; ++it) {
        k_iter<<<NN, 128>>>(src, bi, bf, bo, bg);
        src ^= 1;
    }

    // Transpose result back to (B,N)
    k_out<<<tg, tb>>>((float*)d_out);
}

// round 5
// speedup vs baseline: 2.5083x; 1.3564x over previous
#include <cuda_runtime.h>
#include <cuda_fp16.h>

// Problem constants
#define NN    16384
#define BB    512
#define NNZE  131072
#define CAP   64                     // padded CSC capacity per column
#define NB    (NN * (size_t)BB)

// Scratch (device globals — no runtime allocation allowed)
__device__ __half g_ha[NB];          // h ping buffer, fp16, (N, B) layout
__device__ __half g_hb[NB];          // h pong buffer, fp16, (N, B) layout
__device__ float  g_hf[NB];          // final h, fp32, (N, B) layout
__device__ float  g_c[NB];           // cell state, fp32, (N, B) layout
__device__ int    g_cnt[NN];         // per-column counts (atomic fill cursors)
__device__ float2 g_ent[NN * CAP];   // padded CSC entries: {row_as_float_bits, val}
__device__ int    g_is64;            // 1 if sparse_indices is int64, 0 if int32

// ---------------------------------------------------------------------------
// Fast gate math: MUFU.TANH (1 op), sigmoid via tanh identity.
// ---------------------------------------------------------------------------
__device__ __forceinline__ float tanh_ap(float x) {
    float y;
    asm("tanh.approx.f32 %0, %1;" : "=f"(y) : "f"(x));
    return y;
}
__device__ __forceinline__ float sig_ap(float x) {
    return fmaf(0.5f, tanh_ap(0.5f * x), 0.5f);
}

// ---------------------------------------------------------------------------
// Index dtype detection (int64 high words are all zero).
// ---------------------------------------------------------------------------
__global__ void k_detect(const int* __restrict__ p) {
    int t = threadIdx.x;
    int nz = 0;
#pragma unroll
    for (int i = 0; i < 16; i++) nz |= p[2 * (t + 32 * i) + 1];
    unsigned m = __ballot_sync(0xffffffffu, nz != 0);
    if (t == 0) g_is64 = (m == 0) ? 1 : 0;
}

__device__ __forceinline__ void get_rc(const void* si, int e, int& r, int& c) {
    if (g_is64) {
        const long long* q = (const long long*)si;
        r = (int)q[2 * e];
        c = (int)q[2 * e + 1];
    } else {
        const int* q = (const int*)si;
        r = q[2 * e];
        c = q[2 * e + 1];
    }
}

// ---------------------------------------------------------------------------
// Padded CSC build.
// ---------------------------------------------------------------------------
__global__ void k_zero_cnt() {
    g_cnt[blockIdx.x * 1024 + threadIdx.x] = 0;
}

__global__ void k_build(const void* __restrict__ si, const float* __restrict__ kv) {
    int e = blockIdx.x * 256 + threadIdx.x;
    int r, c;
    get_rc(si, e, r, c);
    int p = atomicAdd(&g_cnt[c], 1);
    if (p < CAP) {
        g_ent[(c << 6) + p] = make_float2(__int_as_float(r), kv[e]);
    }
}

// ---------------------------------------------------------------------------
// Transpose in: x (B,N) fp32 -> g_ha (N,B) fp16. 32x32 tiles, block (32,8).
// ---------------------------------------------------------------------------
__global__ void k_init(const float* __restrict__ x) {
    __shared__ float tile[32][33];
    int nb = blockIdx.x, bb = blockIdx.y;
    int tx = threadIdx.x, ty = threadIdx.y;
#pragma unroll
    for (int i = 0; i < 4; i++) {
        int b = bb * 32 + ty + i * 8;
        int n = nb * 32 + tx;
        tile[ty + i * 8][tx] = x[(size_t)b * NN + n];
    }
    __syncthreads();
#pragma unroll
    for (int i = 0; i < 4; i++) {
        int n = nb * 32 + ty + i * 8;
        int b = bb * 32 + tx;
        g_ha[(size_t)n * BB + b] = __float2half_rn(tile[tx][ty + i * 8]);
    }
}

// Transpose out: g_hf (N,B) fp32 -> out (B,N) fp32.
__global__ void k_out(float* __restrict__ out) {
    __shared__ float tile[32][33];
    int nb = blockIdx.x, bb = blockIdx.y;
    int tx = threadIdx.x, ty = threadIdx.y;
#pragma unroll
    for (int i = 0; i < 4; i++) {
        int n = nb * 32 + ty + i * 8;
        int b = bb * 32 + tx;
        tile[ty + i * 8][tx] = g_hf[(size_t)n * BB + b];
    }
    __syncthreads();
#pragma unroll
    for (int i = 0; i < 4; i++) {
        int b = bb * 32 + ty + i * 8;
        int n = nb * 32 + tx;
        out[(size_t)b * NN + n] = tile[tx][ty + i * 8];
    }
}

// ---------------------------------------------------------------------------
// One reservoir iteration: fused gather-SpMM (padded CSC, fp16 h) + LSTM gates.
// One block per output column c; 128 threads x 4 batch elems covers B=512.
// SRC: 0 = read g_ha, 1 = read g_hb. FIRST: c starts at 0 (no read).
// LAST: write fp32 h to g_hf, skip c write.
// ---------------------------------------------------------------------------
template<int SRC, bool FIRST, bool LAST>
__global__ void __launch_bounds__(128) k_iter(
    const float* __restrict__ bi, const float* __restrict__ bf,
    const float* __restrict__ bo, const float* __restrict__ bg)
{
    int c = blockIdx.x;
    int t = threadIdx.x;
    const __half* __restrict__ hin = SRC ? g_hb : g_ha;
    __half* __restrict__ hout      = SRC ? g_ha : g_hb;

    int cnt = __ldg(&g_cnt[c]);
    const float2* __restrict__ ep = g_ent + (c << 6);

    int boff = t << 2;                    // 4 batch elements per thread
    float4 acc = make_float4(0.f, 0.f, 0.f, 0.f);
    for (int e = 0; e < cnt; ++e) {
        float2 en = __ldg(&ep[e]);
        int   r = __float_as_int(en.x);
        float v = en.y;
        uint2 u = *reinterpret_cast<const uint2*>(hin + ((r << 9) + boff));
        float2 f0 = __half22float2(*reinterpret_cast<__half2*>(&u.x));
        float2 f1 = __half22float2(*reinterpret_cast<__half2*>(&u.y));
        acc.x = fmaf(v, f0.x, acc.x);
        acc.y = fmaf(v, f0.y, acc.y);
        acc.z = fmaf(v, f1.x, acc.z);
        acc.w = fmaf(v, f1.y, acc.w);
    }

    float vbi = __ldg(&bi[c]), vbf = __ldg(&bf[c]);
    float vbo = __ldg(&bo[c]), vbg = __ldg(&bg[c]);

    size_t o = ((size_t)c << 9) + boff;

    float z[4]  = {acc.x, acc.y, acc.z, acc.w};
    float co[4] = {0.f, 0.f, 0.f, 0.f};
    if (!FIRST) {
        float4 cold = *reinterpret_cast<const float4*>(g_c + o);
        co[0] = cold.x; co[1] = cold.y; co[2] = cold.z; co[3] = cold.w;
    }

    float cn[4], hn[4];
#pragma unroll
    for (int k = 0; k < 4; k++) {
        float ii = sig_ap(z[k] + vbi);
        float oo = sig_ap(z[k] + vbo);
        float gg = tanh_ap(z[k] + vbg);
        float ig = ii * gg;
        if (FIRST) {
            cn[k] = ig;
        } else {
            float ff = sig_ap(z[k] + vbf);
            cn[k] = fmaf(ff, co[k], ig);
        }
        hn[k] = oo * tanh_ap(cn[k]);
    }

    if (!LAST) {
        *reinterpret_cast<float4*>(g_c + o) = make_float4(cn[0], cn[1], cn[2], cn[3]);
        __half2 h0 = __float22half2_rn(make_float2(hn[0], hn[1]));
        __half2 h1 = __float22half2_rn(make_float2(hn[2], hn[3]));
        uint2 u;
        u.x = *reinterpret_cast<unsigned*>(&h0);
        u.y = *reinterpret_cast<unsigned*>(&h1);
        *reinterpret_cast<uint2*>(hout + o) = u;
    } else {
        *reinterpret_cast<float4*>(g_hf + o) = make_float4(hn[0], hn[1], hn[2], hn[3]);
    }
}

// ---------------------------------------------------------------------------
// Launch
// ---------------------------------------------------------------------------
extern "C" void kernel_launch(void* const* d_in, const int* in_sizes, int n_in,
                              void* d_out, int out_size)
{
    const float* x  = (const float*)d_in[0];
    const float* kv = (const float*)d_in[1];
    const float* bi = (const float*)d_in[2];
    const float* bf = (const float*)d_in[3];
    const float* bo = (const float*)d_in[4];
    const float* bg = (const float*)d_in[5];
    const void*  si = d_in[6];

    // Sparse preprocessing
    k_detect<<<1, 32>>>((const int*)si);
    k_zero_cnt<<<NN / 1024, 1024>>>();
    k_build<<<NNZE / 256, 256>>>(si, kv);

    // Transpose input to (N,B) fp16 (no c-zero needed; iter0 assumes c=0)
    dim3 tb(32, 8);
    dim3 tg(NN / 32, BB / 32);
    k_init<<<tg, tb>>>(x);

    // 4 reservoir iterations: ha -> hb -> ha -> hb -> g_hf (fp32)
    k_iter<0, true,  false><<<NN, 128>>>(bi, bf, bo, bg);
    k_iter<1, false, false><<<NN, 128>>>(bi, bf, bo, bg);
    k_iter<0, false, false><<<NN, 128>>>(bi, bf, bo, bg);
    k_iter<1, false, true ><<<NN, 128>>>(bi, bf, bo, bg);

    // Transpose result back to (B,N) fp32
    k_out<<<tg, tb>>>((float*)d_out);
}

// round 6
// speedup vs baseline: 2.7499x; 1.0963x over previous
#include <cuda_runtime.h>
#include <cuda_fp16.h>

// Problem constants
#define NN    16384
#define BB    512
#define NNZE  131072
#define CAP   64                     // padded CSC capacity per column
#define NB    (NN * (size_t)BB)

// Scratch (device globals — no runtime allocation allowed)
__device__ __half g_ha[NB];          // h ping buffer, fp16, (N, B) layout
__device__ __half g_hb[NB];          // h pong buffer, fp16, (N, B) layout
__device__ __half g_c16[NB];         // cell state, fp16, (N, B) layout
__device__ int    g_cnt[NN];         // per-column counts (atomic fill cursors)
__device__ float2 g_ent[NN * CAP];   // padded CSC entries: {row_as_float_bits, val}
__device__ int    g_is64;            // 1 if sparse_indices is int64, 0 if int32

// ---------------------------------------------------------------------------
// Fast gate math: MUFU.TANH (1 op), sigmoid via tanh identity.
// ---------------------------------------------------------------------------
__device__ __forceinline__ float tanh_ap(float x) {
    float y;
    asm("tanh.approx.f32 %0, %1;" : "=f"(y) : "f"(x));
    return y;
}
__device__ __forceinline__ float sig_ap(float x) {
    return fmaf(0.5f, tanh_ap(0.5f * x), 0.5f);
}

// ---------------------------------------------------------------------------
// Preprocessing kernel 1: zero counts everywhere; block 0 warp 0 also does
// index dtype detection (int64 high words are all zero).
// Grid 16 x 1024.
// ---------------------------------------------------------------------------
__global__ void k_pre(const int* __restrict__ p) {
    int t = threadIdx.x;
    g_cnt[blockIdx.x * 1024 + t] = 0;
    if (blockIdx.x == 0 && t < 32) {
        int nz = 0;
#pragma unroll
        for (int i = 0; i < 16; i++) nz |= p[2 * (t + 32 * i) + 1];
        unsigned m = __ballot_sync(0xffffffffu, nz != 0);
        if (t == 0) g_is64 = (m == 0) ? 1 : 0;
    }
}

__device__ __forceinline__ void get_rc(const void* si, int e, int& r, int& c) {
    if (g_is64) {
        const long long* q = (const long long*)si;
        r = (int)q[2 * e];
        c = (int)q[2 * e + 1];
    } else {
        const int* q = (const int*)si;
        r = q[2 * e];
        c = q[2 * e + 1];
    }
}

// ---------------------------------------------------------------------------
// Padded CSC build (single atomic-fill pass).
// ---------------------------------------------------------------------------
__global__ void k_build(const void* __restrict__ si, const float* __restrict__ kv) {
    int e = blockIdx.x * 256 + threadIdx.x;
    int r, c;
    get_rc(si, e, r, c);
    int p = atomicAdd(&g_cnt[c], 1);
    if (p < CAP) {
        g_ent[(c << 6) + p] = make_float2(__int_as_float(r), kv[e]);
    }
}

// ---------------------------------------------------------------------------
// Transpose in: x (B,N) fp32 -> g_ha (N,B) fp16.
// Tile: 64 b x 32 n. Block (32,8). Grid (N/32, B/64).
// Load coalesced fp32; store half2 (128B per warp).
// ---------------------------------------------------------------------------
__global__ void k_init(const float* __restrict__ x) {
    __shared__ float tile[64][33];           // [b_local][n_local]
    int nb = blockIdx.x, bb = blockIdx.y;
    int tx = threadIdx.x, ty = threadIdx.y;
#pragma unroll
    for (int i = 0; i < 8; i++) {
        int b = bb * 64 + ty + i * 8;
        int n = nb * 32 + tx;
        tile[ty + i * 8][tx] = x[(size_t)b * NN + n];
    }
    __syncthreads();
    // write: warp ty handles n rows; lane tx writes half2 (2 b's)
#pragma unroll
    for (int i = 0; i < 4; i++) {
        int nl = ty + i * 8;
        int n  = nb * 32 + nl;
        int bl = tx * 2;
        __half2 hv = __float22half2_rn(make_float2(tile[bl][nl], tile[bl + 1][nl]));
        *reinterpret_cast<__half2*>(g_ha + (size_t)n * BB + bb * 64 + bl) = hv;
    }
}

// ---------------------------------------------------------------------------
// Transpose out: g_ha (N,B) fp16 -> out (B,N) fp32.
// Tile: 64 b x 32 n. Block (32,8). Grid (N/32, B/64).
// Load half2 (128B per warp); store coalesced fp32.
// ---------------------------------------------------------------------------
__global__ void k_out(float* __restrict__ out) {
    __shared__ float tile[64][33];           // [b_local][n_local]
    int nb = blockIdx.x, bb = blockIdx.y;
    int tx = threadIdx.x, ty = threadIdx.y;
#pragma unroll
    for (int i = 0; i < 4; i++) {
        int nl = ty + i * 8;
        int n  = nb * 32 + nl;
        int bl = tx * 2;
        __half2 hv = *reinterpret_cast<const __half2*>(g_ha + (size_t)n * BB + bb * 64 + bl);
        float2 f = __half22float2(hv);
        tile[bl][nl]     = f.x;
        tile[bl + 1][nl] = f.y;
    }
    __syncthreads();
#pragma unroll
    for (int i = 0; i < 8; i++) {
        int b = bb * 64 + ty + i * 8;
        int n = nb * 32 + tx;
        out[(size_t)b * NN + n] = tile[ty + i * 8][tx];
    }
}

// ---------------------------------------------------------------------------
// One reservoir iteration: fused gather-SpMM (padded CSC, fp16 h) + LSTM gates.
// One block per output column c; 128 threads x 4 batch elems covers B=512.
// SRC: 0 = read g_ha, 1 = read g_hb. FIRST: c starts at 0 (skip c read).
// LAST: skip c write.
// ---------------------------------------------------------------------------
template<int SRC, bool FIRST, bool LAST>
__global__ void __launch_bounds__(128) k_iter(
    const float* __restrict__ bi, const float* __restrict__ bf,
    const float* __restrict__ bo, const float* __restrict__ bg)
{
    int c = blockIdx.x;
    int t = threadIdx.x;
    const __half* __restrict__ hin = SRC ? g_hb : g_ha;
    __half* __restrict__ hout      = SRC ? g_ha : g_hb;

    int cnt = __ldg(&g_cnt[c]);
    const float2* __restrict__ ep = g_ent + (c << 6);

    int boff = t << 2;                    // 4 batch elements per thread
    float4 acc = make_float4(0.f, 0.f, 0.f, 0.f);
    for (int e = 0; e < cnt; ++e) {
        float2 en = __ldg(&ep[e]);
        int   r = __float_as_int(en.x);
        float v = en.y;
        uint2 u = *reinterpret_cast<const uint2*>(hin + ((r << 9) + boff));
        float2 f0 = __half22float2(*reinterpret_cast<__half2*>(&u.x));
        float2 f1 = __half22float2(*reinterpret_cast<__half2*>(&u.y));
        acc.x = fmaf(v, f0.x, acc.x);
        acc.y = fmaf(v, f0.y, acc.y);
        acc.z = fmaf(v, f1.x, acc.z);
        acc.w = fmaf(v, f1.y, acc.w);
    }

    float vbi = __ldg(&bi[c]), vbf = __ldg(&bf[c]);
    float vbo = __ldg(&bo[c]), vbg = __ldg(&bg[c]);

    size_t o = ((size_t)c << 9) + boff;

    float z[4]  = {acc.x, acc.y, acc.z, acc.w};
    float co[4] = {0.f, 0.f, 0.f, 0.f};
    if (!FIRST) {
        uint2 cu = *reinterpret_cast<const uint2*>(g_c16 + o);
        float2 c01 = __half22float2(*reinterpret_cast<__half2*>(&cu.x));
        float2 c23 = __half22float2(*reinterpret_cast<__half2*>(&cu.y));
        co[0] = c01.x; co[1] = c01.y; co[2] = c23.x; co[3] = c23.y;
    }

    float cn[4], hn[4];
#pragma unroll
    for (int k = 0; k < 4; k++) {
        float ii = sig_ap(z[k] + vbi);
        float oo = sig_ap(z[k] + vbo);
        float gg = tanh_ap(z[k] + vbg);
        float ig = ii * gg;
        if (FIRST) {
            cn[k] = ig;
        } else {
            float ff = sig_ap(z[k] + vbf);
            cn[k] = fmaf(ff, co[k], ig);
        }
        hn[k] = oo * tanh_ap(cn[k]);
    }

    if (!LAST) {
        __half2 c0 = __float22half2_rn(make_float2(cn[0], cn[1]));
        __half2 c1 = __float22half2_rn(make_float2(cn[2], cn[3]));
        uint2 cu;
        cu.x = *reinterpret_cast<unsigned*>(&c0);
        cu.y = *reinterpret_cast<unsigned*>(&c1);
        *reinterpret_cast<uint2*>(g_c16 + o) = cu;
    }

    __half2 h0 = __float22half2_rn(make_float2(hn[0], hn[1]));
    __half2 h1 = __float22half2_rn(make_float2(hn[2], hn[3]));
    uint2 hu;
    hu.x = *reinterpret_cast<unsigned*>(&h0);
    hu.y = *reinterpret_cast<unsigned*>(&h1);
    *reinterpret_cast<uint2*>(hout + o) = hu;
}

// ---------------------------------------------------------------------------
// Launch
// ---------------------------------------------------------------------------
extern "C" void kernel_launch(void* const* d_in, const int* in_sizes, int n_in,
                              void* d_out, int out_size)
{
    const float* x  = (const float*)d_in[0];
    const float* kv = (const float*)d_in[1];
    const float* bi = (const float*)d_in[2];
    const float* bf = (const float*)d_in[3];
    const float* bo = (const float*)d_in[4];
    const float* bg = (const float*)d_in[5];
    const void*  si = d_in[6];

    // Sparse preprocessing: zero counts + dtype detect, then atomic fill
    k_pre<<<NN / 1024, 1024>>>((const int*)si);
    k_build<<<NNZE / 256, 256>>>(si, kv);

    // Transpose input to (N,B) fp16
    dim3 tb(32, 8);
    dim3 tg(NN / 32, BB / 64);
    k_init<<<tg, tb>>>(x);

    // 4 reservoir iterations: ha -> hb -> ha -> hb -> ha (all fp16)
    k_iter<0, true,  false><<<NN, 128>>>(bi, bf, bo, bg);
    k_iter<1, false, false><<<NN, 128>>>(bi, bf, bo, bg);
    k_iter<0, false, false><<<NN, 128>>>(bi, bf, bo, bg);
    k_iter<1, false, true ><<<NN, 128>>>(bi, bf, bo, bg);

    // Transpose result (g_ha) back to (B,N) fp32
    k_out<<<tg, tb>>>((float*)d_out);
}

// round 7
// speedup vs baseline: 3.2136x; 1.1686x over previous
#include <cuda_runtime.h>
#include <cuda_fp16.h>

// Problem constants
#define NN    16384
#define BB    512
#define NNZE  131072
#define CAP   64                     // padded CSC capacity per column
#define NB    (NN * (size_t)BB)

// Scratch (device globals — no runtime allocation allowed)
__device__ __half g_ha[NB];          // h ping buffer, fp16, (N, B) layout
__device__ __half g_hb[NB];          // h pong buffer, fp16, (N, B) layout
__device__ __half g_c16[NB];         // cell state, fp16, (N, B) layout
__device__ int    g_cnt[NN];         // per-column counts (padded to mult of 4)
__device__ float2 g_ent[NN * CAP];   // entries: {row_as_bits, val_as_half2_bits}
__device__ int    g_is64;            // 1 if sparse_indices is int64, 0 if int32

// ---------------------------------------------------------------------------
// Fast gate math: MUFU.TANH (1 op), sigmoid via tanh identity.
// ---------------------------------------------------------------------------
__device__ __forceinline__ float tanh_ap(float x) {
    float y;
    asm("tanh.approx.f32 %0, %1;" : "=f"(y) : "f"(x));
    return y;
}
__device__ __forceinline__ float sig_ap(float x) {
    return fmaf(0.5f, tanh_ap(0.5f * x), 0.5f);
}

// ---------------------------------------------------------------------------
// Preprocessing: zero counts; block 0 warp 0 detects index dtype
// (int64 high words are all zero).
// ---------------------------------------------------------------------------
__global__ void k_pre(const int* __restrict__ p) {
    int t = threadIdx.x;
    g_cnt[blockIdx.x * 1024 + t] = 0;
    if (blockIdx.x == 0 && t < 32) {
        int nz = 0;
#pragma unroll
        for (int i = 0; i < 16; i++) nz |= p[2 * (t + 32 * i) + 1];
        unsigned m = __ballot_sync(0xffffffffu, nz != 0);
        if (t == 0) g_is64 = (m == 0) ? 1 : 0;
    }
}

__device__ __forceinline__ void get_rc(const void* si, int e, int& r, int& c) {
    if (g_is64) {
        const long long* q = (const long long*)si;
        r = (int)q[2 * e];
        c = (int)q[2 * e + 1];
    } else {
        const int* q = (const int*)si;
        r = q[2 * e];
        c = q[2 * e + 1];
    }
}

// ---------------------------------------------------------------------------
// Padded CSC build: value stored as duplicated half2 bits.
// ---------------------------------------------------------------------------
__global__ void k_build(const void* __restrict__ si, const float* __restrict__ kv) {
    int e = blockIdx.x * 256 + threadIdx.x;
    int r, c;
    get_rc(si, e, r, c);
    int p = atomicAdd(&g_cnt[c], 1);
    if (p < CAP) {
        __half2 h2 = __half2half2(__float2half_rn(kv[e]));
        g_ent[(c << 6) + p] =
            make_float2(__int_as_float(r), __uint_as_float(*reinterpret_cast<unsigned*>(&h2)));
    }
}

// Pad each column's entry list to a multiple of 4 with inert {row 0, val 0}.
__global__ void k_pad() {
    int c = blockIdx.x * 256 + threadIdx.x;
    int cnt = g_cnt[c];
    int cnt4 = (cnt + 3) & ~3;
    for (int p = cnt; p < cnt4; ++p)
        g_ent[(c << 6) + p] = make_float2(0.f, 0.f);
    g_cnt[c] = cnt4;
}

// ---------------------------------------------------------------------------
// Transpose in: x (B,N) fp32 -> g_ha (N,B) fp16. Tile 64b x 32n, block (32,8).
// ---------------------------------------------------------------------------
__global__ void k_init(const float* __restrict__ x) {
    __shared__ float tile[64][33];           // [b_local][n_local]
    int nb = blockIdx.x, bb = blockIdx.y;
    int tx = threadIdx.x, ty = threadIdx.y;
#pragma unroll
    for (int i = 0; i < 8; i++) {
        int b = bb * 64 + ty + i * 8;
        int n = nb * 32 + tx;
        tile[ty + i * 8][tx] = x[(size_t)b * NN + n];
    }
    __syncthreads();
#pragma unroll
    for (int i = 0; i < 4; i++) {
        int nl = ty + i * 8;
        int n  = nb * 32 + nl;
        int bl = tx * 2;
        __half2 hv = __float22half2_rn(make_float2(tile[bl][nl], tile[bl + 1][nl]));
        *reinterpret_cast<__half2*>(g_ha + (size_t)n * BB + bb * 64 + bl) = hv;
    }
}

// Transpose out: g_ha (N,B) fp16 -> out (B,N) fp32.
__global__ void k_out(float* __restrict__ out) {
    __shared__ float tile[64][33];
    int nb = blockIdx.x, bb = blockIdx.y;
    int tx = threadIdx.x, ty = threadIdx.y;
#pragma unroll
    for (int i = 0; i < 4; i++) {
        int nl = ty + i * 8;
        int n  = nb * 32 + nl;
        int bl = tx * 2;
        __half2 hv = *reinterpret_cast<const __half2*>(g_ha + (size_t)n * BB + bb * 64 + bl);
        float2 f = __half22float2(hv);
        tile[bl][nl]     = f.x;
        tile[bl + 1][nl] = f.y;
    }
    __syncthreads();
#pragma unroll
    for (int i = 0; i < 8; i++) {
        int b = bb * 64 + ty + i * 8;
        int n = nb * 32 + tx;
        out[(size_t)b * NN + n] = tile[ty + i * 8][tx];
    }
}

// ---------------------------------------------------------------------------
// One reservoir iteration. Block = 128 threads = 2 columns x 64 threads.
// Each thread: 8 batch elems. Mainloop: HFMA2 accumulation, 4 entries per
// unrolled step, entries fetched 2-per-LDG.128.
// ---------------------------------------------------------------------------
template<int SRC, bool FIRST, bool LAST>
__global__ void __launch_bounds__(128) k_iter(
    const float* __restrict__ bi, const float* __restrict__ bf,
    const float* __restrict__ bo, const float* __restrict__ bg)
{
    int t  = threadIdx.x;
    int c  = (blockIdx.x << 1) + (t >> 6);
    int lt = t & 63;
    const __half* __restrict__ hin = SRC ? g_hb : g_ha;
    __half* __restrict__ hout      = SRC ? g_ha : g_hb;

    int cnt = __ldg(&g_cnt[c]);                  // multiple of 4
    const float4* __restrict__ ep = reinterpret_cast<const float4*>(g_ent + (c << 6));

    int boff = lt << 3;                          // 8 batch elements per thread
    __half2 a0 = __half2half2(__ushort_as_half(0));
    __half2 a1 = a0, a2 = a0, a3 = a0;

    for (int e = 0; e < cnt; e += 4) {
        float4 e01 = __ldg(&ep[(e >> 1)]);
        float4 e23 = __ldg(&ep[(e >> 1) + 1]);
#pragma unroll
        for (int k = 0; k < 4; ++k) {
            float rb = (k == 0) ? e01.x : (k == 1) ? e01.z : (k == 2) ? e23.x : e23.z;
            float vb = (k == 0) ? e01.y : (k == 1) ? e01.w : (k == 2) ? e23.y : e23.w;
            int r = __float_as_int(rb);
            unsigned vu = __float_as_uint(vb);
            __half2 v2 = *reinterpret_cast<__half2*>(&vu);
            uint4 u = *reinterpret_cast<const uint4*>(hin + ((r << 9) + boff));
            a0 = __hfma2(v2, *reinterpret_cast<__half2*>(&u.x), a0);
            a1 = __hfma2(v2, *reinterpret_cast<__half2*>(&u.y), a1);
            a2 = __hfma2(v2, *reinterpret_cast<__half2*>(&u.z), a2);
            a3 = __hfma2(v2, *reinterpret_cast<__half2*>(&u.w), a3);
        }
    }

    float z[8];
    {
        float2 f0 = __half22float2(a0), f1 = __half22float2(a1);
        float2 f2 = __half22float2(a2), f3 = __half22float2(a3);
        z[0] = f0.x; z[1] = f0.y; z[2] = f1.x; z[3] = f1.y;
        z[4] = f2.x; z[5] = f2.y; z[6] = f3.x; z[7] = f3.y;
    }

    float vbi = __ldg(&bi[c]), vbf = __ldg(&bf[c]);
    float vbo = __ldg(&bo[c]), vbg = __ldg(&bg[c]);

    size_t o = ((size_t)c << 9) + boff;

    float co[8] = {0.f, 0.f, 0.f, 0.f, 0.f, 0.f, 0.f, 0.f};
    if (!FIRST) {
        uint4 cu = *reinterpret_cast<const uint4*>(g_c16 + o);
        float2 c0 = __half22float2(*reinterpret_cast<__half2*>(&cu.x));
        float2 c1 = __half22float2(*reinterpret_cast<__half2*>(&cu.y));
        float2 c2 = __half22float2(*reinterpret_cast<__half2*>(&cu.z));
        float2 c3 = __half22float2(*reinterpret_cast<__half2*>(&cu.w));
        co[0] = c0.x; co[1] = c0.y; co[2] = c1.x; co[3] = c1.y;
        co[4] = c2.x; co[5] = c2.y; co[6] = c3.x; co[7] = c3.y;
    }

    float cn[8], hn[8];
#pragma unroll
    for (int k = 0; k < 8; k++) {
        float ii = sig_ap(z[k] + vbi);
        float oo = sig_ap(z[k] + vbo);
        float gg = tanh_ap(z[k] + vbg);
        float ig = ii * gg;
        if (FIRST) {
            cn[k] = ig;
        } else {
            float ff = sig_ap(z[k] + vbf);
            cn[k] = fmaf(ff, co[k], ig);
        }
        hn[k] = oo * tanh_ap(cn[k]);
    }

    if (!LAST) {
        uint4 cu;
        __half2 q0 = __float22half2_rn(make_float2(cn[0], cn[1]));
        __half2 q1 = __float22half2_rn(make_float2(cn[2], cn[3]));
        __half2 q2 = __float22half2_rn(make_float2(cn[4], cn[5]));
        __half2 q3 = __float22half2_rn(make_float2(cn[6], cn[7]));
        cu.x = *reinterpret_cast<unsigned*>(&q0);
        cu.y = *reinterpret_cast<unsigned*>(&q1);
        cu.z = *reinterpret_cast<unsigned*>(&q2);
        cu.w = *reinterpret_cast<unsigned*>(&q3);
        *reinterpret_cast<uint4*>(g_c16 + o) = cu;
    }

    {
        uint4 hu;
        __half2 q0 = __float22half2_rn(make_float2(hn[0], hn[1]));
        __half2 q1 = __float22half2_rn(make_float2(hn[2], hn[3]));
        __half2 q2 = __float22half2_rn(make_float2(hn[4], hn[5]));
        __half2 q3 = __float22half2_rn(make_float2(hn[6], hn[7]));
        hu.x = *reinterpret_cast<unsigned*>(&q0);
        hu.y = *reinterpret_cast<unsigned*>(&q1);
        hu.z = *reinterpret_cast<unsigned*>(&q2);
        hu.w = *reinterpret_cast<unsigned*>(&q3);
        *reinterpret_cast<uint4*>(hout + o) = hu;
    }
}

// ---------------------------------------------------------------------------
// Launch
// ---------------------------------------------------------------------------
extern "C" void kernel_launch(void* const* d_in, const int* in_sizes, int n_in,
                              void* d_out, int out_size)
{
    const float* x  = (const float*)d_in[0];
    const float* kv = (const float*)d_in[1];
    const float* bi = (const float*)d_in[2];
    const float* bf = (const float*)d_in[3];
    const float* bo = (const float*)d_in[4];
    const float* bg = (const float*)d_in[5];
    const void*  si = d_in[6];

    // Sparse preprocessing
    k_pre<<<NN / 1024, 1024>>>((const int*)si);
    k_build<<<NNZE / 256, 256>>>(si, kv);
    k_pad<<<NN / 256, 256>>>();

    // Transpose input to (N,B) fp16
    dim3 tb(32, 8);
    dim3 tg(NN / 32, BB / 64);
    k_init<<<tg, tb>>>(x);

    // 4 reservoir iterations: ha -> hb -> ha -> hb -> ha (all fp16)
    k_iter<0, true,  false><<<NN / 2, 128>>>(bi, bf, bo, bg);
    k_iter<1, false, false><<<NN / 2, 128>>>(bi, bf, bo, bg);
    k_iter<0, false, false><<<NN / 2, 128>>>(bi, bf, bo, bg);
    k_iter<1, false, true ><<<NN / 2, 128>>>(bi, bf, bo, bg);

    // Transpose result (g_ha) back to (B,N) fp32
    k_out<<<tg, tb>>>((float*)d_out);
}

// round 9
// speedup vs baseline: 3.2722x; 1.0182x over previous
#include <cuda_runtime.h>
#include <cuda_fp16.h>

// Problem constants
#define NN    16384
#define BB    512
#define NNZE  131072
#define CAP   64                     // padded CSC capacity per column
#define NB    (NN * (size_t)BB)

// Scratch (device globals — no runtime allocation allowed)
__device__ __half g_ha[NB];          // h ping buffer, fp16, (N, B) layout
__device__ __half g_hb[NB];          // h pong buffer, fp16, (N, B) layout
__device__ __half g_c16[NB];         // cell state, fp16, (N, B) layout
__device__ int    g_cnt[NN];         // per-column counts (raw)
__device__ float2 g_ent[NN * CAP];   // entries: {row_as_bits, val_as_half2_bits}
__device__ int    g_is64;            // 1 if sparse_indices is int64, 0 if int32

// ---------------------------------------------------------------------------
// Fast gate math: MUFU.TANH (1 op), sigmoid via tanh identity.
// ---------------------------------------------------------------------------
__device__ __forceinline__ float tanh_ap(float x) {
    float y;
    asm("tanh.approx.f32 %0, %1;" : "=f"(y) : "f"(x));
    return y;
}
__device__ __forceinline__ float sig_ap(float x) {
    return fmaf(0.5f, tanh_ap(0.5f * x), 0.5f);
}

// ---------------------------------------------------------------------------
// Preprocessing: zero ALL entry slots (pad slots stay {0,0} = inert),
// zero counts, detect index dtype (int64 high words are all zero).
// Grid 512 x 1024: each thread zeroes one float4 (2 entries).
// ---------------------------------------------------------------------------
__global__ void k_pre(const int* __restrict__ p) {
    unsigned idx = blockIdx.x * 1024 + threadIdx.x;
    reinterpret_cast<float4*>(g_ent)[idx] = make_float4(0.f, 0.f, 0.f, 0.f);
    if (idx < NN) g_cnt[idx] = 0;
    if (blockIdx.x == 0 && threadIdx.x < 32) {
        int t = threadIdx.x;
        int nz = 0;
#pragma unroll
        for (int i = 0; i < 16; i++) nz |= p[2 * (t + 32 * i) + 1];
        unsigned m = __ballot_sync(0xffffffffu, nz != 0);
        if (t == 0) g_is64 = (m == 0) ? 1 : 0;
    }
}

__device__ __forceinline__ void get_rc(const void* si, int e, int& r, int& c) {
    if (g_is64) {
        const long long* q = (const long long*)si;
        r = (int)q[2 * e];
        c = (int)q[2 * e + 1];
    } else {
        const int* q = (const int*)si;
        r = q[2 * e];
        c = q[2 * e + 1];
    }
}

// ---------------------------------------------------------------------------
// Padded CSC build: value stored as duplicated half2 bits.
// ---------------------------------------------------------------------------
__global__ void k_build(const void* __restrict__ si, const float* __restrict__ kv) {
    int e = blockIdx.x * 256 + threadIdx.x;
    int r, c;
    get_rc(si, e, r, c);
    int p = atomicAdd(&g_cnt[c], 1);
    if (p < CAP) {
        __half2 h2 = __half2half2(__float2half_rn(kv[e]));
        g_ent[(c << 6) + p] =
            make_float2(__int_as_float(r), __uint_as_float(*reinterpret_cast<unsigned*>(&h2)));
    }
}

// ---------------------------------------------------------------------------
// Transpose in: x (B,N) fp32 -> g_ha (N,B) fp16.
// Tile 64b x 64n, block (32,8), grid (N/64, B/64).
// Load phase: float2 (LDG.64, warp = 256B contiguous), STS.64 conflict-free.
// Store phase: half2 STG.32 (warp = 128B contiguous), LDS 2-way.
// ---------------------------------------------------------------------------
__global__ void k_init(const float* __restrict__ x) {
    __shared__ float tile[64][65];           // [b_local][n_local]
    int nb = blockIdx.x, bb = blockIdx.y;
    int tx = threadIdx.x, ty = threadIdx.y;
#pragma unroll
    for (int i = 0; i < 8; i++) {
        int b  = bb * 64 + ty + i * 8;
        int n  = nb * 64 + 2 * tx;
        float2 v = *reinterpret_cast<const float2*>(x + (size_t)b * NN + n);
        tile[ty + i * 8][2 * tx]     = v.x;
        tile[ty + i * 8][2 * tx + 1] = v.y;
    }
    __syncthreads();
#pragma unroll
    for (int i = 0; i < 8; i++) {
        int nl = ty * 8 + i;
        int n  = nb * 64 + nl;
        int bl = 2 * tx;
        __half2 hv = __float22half2_rn(make_float2(tile[bl][nl], tile[bl + 1][nl]));
        *reinterpret_cast<__half2*>(g_ha + (size_t)n * BB + bb * 64 + bl) = hv;
    }
}

// ---------------------------------------------------------------------------
// Transpose out: g_ha (N,B) fp16 -> out (B,N) fp32. Mirror of k_init.
// ---------------------------------------------------------------------------
__global__ void k_out(float* __restrict__ out) {
    __shared__ float tile[64][65];
    int nb = blockIdx.x, bb = blockIdx.y;
    int tx = threadIdx.x, ty = threadIdx.y;
#pragma unroll
    for (int i = 0; i < 8; i++) {
        int nl = ty * 8 + i;
        int n  = nb * 64 + nl;
        int bl = 2 * tx;
        __half2 hv = *reinterpret_cast<const __half2*>(g_ha + (size_t)n * BB + bb * 64 + bl);
        float2 f = __half22float2(hv);
        tile[bl][nl]     = f.x;
        tile[bl + 1][nl] = f.y;
    }
    __syncthreads();
#pragma unroll
    for (int i = 0; i < 8; i++) {
        int b = bb * 64 + ty + i * 8;
        int n = nb * 64 + 2 * tx;
        *reinterpret_cast<float2*>(out + (size_t)b * NN + n) =
            make_float2(tile[ty + i * 8][2 * tx], tile[ty + i * 8][2 * tx + 1]);
    }
}

// ---------------------------------------------------------------------------
// One reservoir iteration. Block = 128 threads = 2 columns x 64 threads.
// Each thread: 8 batch elems. HFMA2 accumulation, 4 entries per unrolled
// step, entries fetched 2-per-LDG.128. cnt rounded up to mult-4 (pad slots
// are zero-valued => inert).
// ---------------------------------------------------------------------------
template<int SRC, bool FIRST, bool LAST>
__global__ void __launch_bounds__(128) k_iter(
    const float* __restrict__ bi, const float* __restrict__ bf,
    const float* __restrict__ bo, const float* __restrict__ bg)
{
    int t  = threadIdx.x;
    int c  = (blockIdx.x << 1) + (t >> 6);
    int lt = t & 63;
    const __half* __restrict__ hin = SRC ? g_hb : g_ha;
    __half* __restrict__ hout      = SRC ? g_ha : g_hb;

    int cnt = (__ldg(&g_cnt[c]) + 3) & ~3;
    const float4* __restrict__ ep = reinterpret_cast<const float4*>(g_ent + (c << 6));

    int boff = lt << 3;                          // 8 batch elements per thread
    __half2 a0 = __half2half2(__ushort_as_half(0));
    __half2 a1 = a0, a2 = a0, a3 = a0;

    for (int e = 0; e < cnt; e += 4) {
        float4 e01 = __ldg(&ep[(e >> 1)]);
        float4 e23 = __ldg(&ep[(e >> 1) + 1]);
#pragma unroll
        for (int k = 0; k < 4; ++k) {
            float rb = (k == 0) ? e01.x : (k == 1) ? e01.z : (k == 2) ? e23.x : e23.z;
            float vb = (k == 0) ? e01.y : (k == 1) ? e01.w : (k == 2) ? e23.y : e23.w;
            int r = __float_as_int(rb);
            unsigned vu = __float_as_uint(vb);
            __half2 v2 = *reinterpret_cast<__half2*>(&vu);
            uint4 u = *reinterpret_cast<const uint4*>(hin + ((r << 9) + boff));
            a0 = __hfma2(v2, *reinterpret_cast<__half2*>(&u.x), a0);
            a1 = __hfma2(v2, *reinterpret_cast<__half2*>(&u.y), a1);
            a2 = __hfma2(v2, *reinterpret_cast<__half2*>(&u.z), a2);
            a3 = __hfma2(v2, *reinterpret_cast<__half2*>(&u.w), a3);
        }
    }

    float z[8];
    {
        float2 f0 = __half22float2(a0), f1 = __half22float2(a1);
        float2 f2 = __half22float2(a2), f3 = __half22float2(a3);
        z[0] = f0.x; z[1] = f0.y; z[2] = f1.x; z[3] = f1.y;
        z[4] = f2.x; z[5] = f2.y; z[6] = f3.x; z[7] = f3.y;
    }

    float vbi = __ldg(&bi[c]), vbf = __ldg(&bf[c]);
    float vbo = __ldg(&bo[c]), vbg = __ldg(&bg[c]);

    size_t o = ((size_t)c << 9) + boff;

    float co[8] = {0.f, 0.f, 0.f, 0.f, 0.f, 0.f, 0.f, 0.f};
    if (!FIRST) {
        uint4 cu = *reinterpret_cast<const uint4*>(g_c16 + o);
        float2 c0 = __half22float2(*reinterpret_cast<__half2*>(&cu.x));
        float2 c1 = __half22float2(*reinterpret_cast<__half2*>(&cu.y));
        float2 c2 = __half22float2(*reinterpret_cast<__half2*>(&cu.z));
        float2 c3 = __half22float2(*reinterpret_cast<__half2*>(&cu.w));
        co[0] = c0.x; co[1] = c0.y; co[2] = c1.x; co[3] = c1.y;
        co[4] = c2.x; co[5] = c2.y; co[6] = c3.x; co[7] = c3.y;
    }

    float cn[8], hn[8];
#pragma unroll
    for (int k = 0; k < 8; k++) {
        float ii = sig_ap(z[k] + vbi);
        float oo = sig_ap(z[k] + vbo);
        float gg = tanh_ap(z[k] + vbg);
        float ig = ii * gg;
        if (FIRST) {
            cn[k] = ig;
        } else {
            float ff = sig_ap(z[k] + vbf);
            cn[k] = fmaf(ff, co[k], ig);
        }
        hn[k] = oo * tanh_ap(cn[k]);
    }

    if (!LAST) {
        uint4 cu;
        __half2 q0 = __float22half2_rn(make_float2(cn[0], cn[1]));
        __half2 q1 = __float22half2_rn(make_float2(cn[2], cn[3]));
        __half2 q2 = __float22half2_rn(make_float2(cn[4], cn[5]));
        __half2 q3 = __float22half2_rn(make_float2(cn[6], cn[7]));
        cu.x = *reinterpret_cast<unsigned*>(&q0);
        cu.y = *reinterpret_cast<unsigned*>(&q1);
        cu.z = *reinterpret_cast<unsigned*>(&q2);
        cu.w = *reinterpret_cast<unsigned*>(&q3);
        *reinterpret_cast<uint4*>(g_c16 + o) = cu;
    }

    {
        uint4 hu;
        __half2 q0 = __float22half2_rn(make_float2(hn[0], hn[1]));
        __half2 q1 = __float22half2_rn(make_float2(hn[2], hn[3]));
        __half2 q2 = __float22half2_rn(make_float2(hn[4], hn[5]));
        __half2 q3 = __float22half2_rn(make_float2(hn[6], hn[7]));
        hu.x = *reinterpret_cast<unsigned*>(&q0);
        hu.y = *reinterpret_cast<unsigned*>(&q1);
        hu.z = *reinterpret_cast<unsigned*>(&q2);
        hu.w = *reinterpret_cast<unsigned*>(&q3);
        *reinterpret_cast<uint4*>(hout + o) = hu;
    }
}

// ---------------------------------------------------------------------------
// Launch
// ---------------------------------------------------------------------------
extern "C" void kernel_launch(void* const* d_in, const int* in_sizes, int n_in,
                              void* d_out, int out_size)
{
    const float* x  = (const float*)d_in[0];
    const float* kv = (const float*)d_in[1];
    const float* bi = (const float*)d_in[2];
    const float* bf = (const float*)d_in[3];
    const float* bo = (const float*)d_in[4];
    const float* bg = (const float*)d_in[5];
    const void*  si = d_in[6];

    // Sparse preprocessing: zero entries+counts (+dtype detect), atomic fill
    k_pre<<<(NN * CAP / 2) / 1024, 1024>>>((const int*)si);
    k_build<<<NNZE / 256, 256>>>(si, kv);

    // Transpose input to (N,B) fp16
    dim3 tb(32, 8);
    dim3 tg(NN / 64, BB / 64);
    k_init<<<tg, tb>>>(x);

    // 4 reservoir iterations: ha -> hb -> ha -> hb -> ha (all fp16)
    k_iter<0, true,  false><<<NN / 2, 128>>>(bi, bf, bo, bg);
    k_iter<1, false, false><<<NN / 2, 128>>>(bi, bf, bo, bg);
    k_iter<0, false, false><<<NN / 2, 128>>>(bi, bf, bo, bg);
    k_iter<1, false, true ><<<NN / 2, 128>>>(bi, bf, bo, bg);

    // Transpose result (g_ha) back to (B,N) fp32
    k_out<<<tg, tb>>>((float*)d_out);
}